// round 15
// baseline (speedup 1.0000x reference)
#include <cuda_runtime.h>
#include <cuda_bf16.h>
#include <cuda_fp16.h>
#include <math.h>
#include <stdint.h>

#define Bb 128
#define Tt 30
#define Vv 10000
#define Hh 512
#define Ff 4096
#define BH (Bb*Hh)
#define TBH (Tt*Bb*Hh)
#define Vpad 10112
#define SZGRU (512*1024)

typedef __nv_bfloat16 bf16;
typedef __nv_bfloat162 bf162;

__device__ float g_h0f[BH], g_h1f[BH], g_u0f[BH], g_u1f[BH];
__device__ float g_Xu0[TBH], g_Xr0[TBH], g_Xc0[TBH];
__device__ float g_ipart[4][BH];

// bf16 operands (init GEMM only)
__device__ __align__(16) bf16 g_vgg_h[Bb*Ff], g_vgg_l[Bb*Ff];
__device__ __align__(16) bf16 g_Win_h[Hh*Ff], g_Win_l[Hh*Ff];

// fp16 activations
__device__ __align__(16) __half g_xembH[TBH];
__device__ __align__(16) __half g_h0H[BH];
__device__ __align__(16) __half g_rh0H[BH];
__device__ __align__(16) __half g_c1H[Bb*1024];
__device__ __align__(16) __half g_c2H[2][Bb*1024];
__device__ __align__(16) __half g_X1ah[TBH];

// fp16 weights
__device__ __align__(16) __half g_WgruH[6*SZGRU];   // [z][N=512, K=1024]
__device__ __align__(16) __half g_WoH[Vpad*Hh];     // [N, K=512]

__device__ __forceinline__ uint32_t smem_u32(const void* p) {
    uint32_t a;
    asm("{ .reg .u64 t; cvta.to.shared.u64 t, %1; cvt.u32.u64 %0, t; }" : "=r"(a) : "l"(p));
    return a;
}
__device__ __forceinline__ void cpasync16(uint32_t dst, const void* src) {
    asm volatile("cp.async.cg.shared.global [%0], [%1], 16;" :: "r"(dst), "l"(src) : "memory");
}
#define CP_COMMIT() asm volatile("cp.async.commit_group;" ::: "memory")
#define CP_WAIT2()  asm volatile("cp.async.wait_group 2;" ::: "memory")
#define CP_WAIT1()  asm volatile("cp.async.wait_group 1;" ::: "memory")
#define CP_WAIT0()  asm volatile("cp.async.wait_group 0;" ::: "memory")
#define LDSM4(R, addr) \
    asm volatile("ldmatrix.sync.aligned.m8n8.x4.shared.b16 {%0,%1,%2,%3}, [%4];" \
        : "=r"((R)[0]), "=r"((R)[1]), "=r"((R)[2]), "=r"((R)[3]) : "r"(addr))

__device__ __forceinline__ void mmaop(float* c, const uint32_t* a, const uint32_t* b) {
    asm volatile("mma.sync.aligned.m16n8k16.row.col.f32.bf16.bf16.f32 "
        "{%0,%1,%2,%3}, {%4,%5,%6,%7}, {%8,%9}, {%0,%1,%2,%3};"
        : "+f"(c[0]), "+f"(c[1]), "+f"(c[2]), "+f"(c[3])
        : "r"(a[0]), "r"(a[1]), "r"(a[2]), "r"(a[3]), "r"(b[0]), "r"(b[1]));
}
__device__ __forceinline__ void mmaop_h(float* c, const uint32_t* a, const uint32_t* b) {
    asm volatile("mma.sync.aligned.m16n8k16.row.col.f32.f16.f16.f32 "
        "{%0,%1,%2,%3}, {%4,%5,%6,%7}, {%8,%9}, {%0,%1,%2,%3};"
        : "+f"(c[0]), "+f"(c[1]), "+f"(c[2]), "+f"(c[3])
        : "r"(a[0]), "r"(a[1]), "r"(a[2]), "r"(a[3]), "r"(b[0]), "r"(b[1]));
}
__device__ __forceinline__ float sigmoidf_(float x) { return 1.0f / (1.0f + expf(-x)); }
__device__ __forceinline__ void sp2(bf16* H, bf16* L, int i, float a, float b) {
    bf16 ha = __float2bfloat16(a), hb = __float2bfloat16(b);
    bf162 hv; hv.x = ha; hv.y = hb;
    bf162 lv; lv.x = __float2bfloat16(a - __bfloat162float(ha));
    lv.y = __float2bfloat16(b - __bfloat162float(hb));
    *(bf162*)&H[i] = hv; *(bf162*)&L[i] = lv;
}
__device__ __forceinline__ void sph(__half* H, int i, float a, float b) {
    __half2 hv; hv.x = __float2half_rn(a); hv.y = __float2half_rn(b);
    *(__half2*)&H[i] = hv;
}

// ---- split-3 bf16 mma GEMM (init only), 2-stage KT=32 ----
#define ROWB 80
template<int TM, int TN, typename Epi>
__device__ __forceinline__ void mma_gemm(
    const bf16* __restrict__ Ah, const bf16* __restrict__ Al, int lda, int m0,
    const bf16* __restrict__ Bh, const bf16* __restrict__ Bl, int ldb, int n0,
    int K, Epi epi)
{
    extern __shared__ char smem[];
    constexpr int ASZ = TM * ROWB, BSZ = TN * ROWB, STG = 2*ASZ + 2*BSZ;
    constexpr int WM = TM / 4, WN = TN / 2, FM = WM / 16, NF = WN / 8;
    constexpr int GG = (NF > 4) ? 4 : NF;
    const uint32_t s0 = smem_u32(smem);
    const int tid = threadIdx.x, lane = tid & 31, wid = tid >> 5;
    const int wm = wid >> 1, wn = wid & 1;
    const int lrow = lane & 15, lhalf = lane >> 4;
    float acc[FM][NF][4] = {};

    auto issue = [&](int ch, int st) {
        uint32_t d = s0 + st * STG;
        int k0 = ch * 32;
        #pragma unroll
        for (int v = tid; v < TM * 4; v += 256) {
            int row = v >> 2, c = v & 3;
            cpasync16(d + row*ROWB + c*16,       Ah + (m0+row)*lda + k0 + c*8);
            cpasync16(d + ASZ + row*ROWB + c*16, Al + (m0+row)*lda + k0 + c*8);
        }
        #pragma unroll
        for (int v = tid; v < TN * 4; v += 256) {
            int row = v >> 2, c = v & 3;
            cpasync16(d + 2*ASZ + row*ROWB + c*16,       Bh + (n0+row)*ldb + k0 + c*8);
            cpasync16(d + 2*ASZ + BSZ + row*ROWB + c*16, Bl + (n0+row)*ldb + k0 + c*8);
        }
        CP_COMMIT();
    };

    const int NC = K / 32;
    issue(0, 0);
    for (int ch = 0; ch < NC; ch++) {
        int st = ch & 1;
        if (ch + 1 < NC) { issue(ch + 1, (ch + 1) & 1); CP_WAIT1(); }
        else CP_WAIT0();
        __syncthreads();
        uint32_t d = s0 + st * STG;
        #pragma unroll
        for (int kk = 0; kk < 2; kk++) {
            uint32_t ah[FM][4], al[FM][4];
            #pragma unroll
            for (int f = 0; f < FM; f++) {
                uint32_t a = d + (wm*WM + f*16 + lrow)*ROWB + lhalf*16 + kk*32;
                LDSM4(ah[f], a);
                LDSM4(al[f], a + ASZ);
            }
            #pragma unroll
            for (int gg = 0; gg < NF; gg += GG) {
                uint32_t bh[GG][2], bl[GG][2];
                #pragma unroll
                for (int g2 = 0; g2 < GG; g2 += 2) {
                    int g = gg + g2;
                    uint32_t b = d + 2*ASZ + (wn*WN + g*8 + lrow)*ROWB + lhalf*16 + kk*32;
                    uint32_t t4[4];
                    LDSM4(t4, b);
                    bh[g2][0]=t4[0]; bh[g2][1]=t4[2]; bh[g2+1][0]=t4[1]; bh[g2+1][1]=t4[3];
                    LDSM4(t4, b + BSZ);
                    bl[g2][0]=t4[0]; bl[g2][1]=t4[2]; bl[g2+1][0]=t4[1]; bl[g2+1][1]=t4[3];
                }
                #pragma unroll
                for (int f = 0; f < FM; f++)
                    #pragma unroll
                    for (int g2 = 0; g2 < GG; g2++) {
                        mmaop(acc[f][gg+g2], ah[f], bh[g2]);
                        mmaop(acc[f][gg+g2], ah[f], bl[g2]);
                        mmaop(acc[f][gg+g2], al[f], bh[g2]);
                    }
            }
        }
        __syncthreads();
    }
    #pragma unroll
    for (int f = 0; f < FM; f++)
        #pragma unroll
        for (int g = 0; g < NF; g++) {
            int r = m0 + wm*WM + f*16 + (lane >> 2);
            int c = n0 + wn*WN + g*8 + (lane & 3)*2;
            epi(r,     c, acc[f][g][0], acc[f][g][1]);
            epi(r + 8, c, acc[f][g][2], acc[f][g][3]);
        }
}

// ---- 1-term fp16 GEMM, 2-stage KT=32 (xpre / logits) ----
template<int TM, int TN, typename Epi>
__device__ __forceinline__ void gemm1_2s(
    const __half* __restrict__ A, int lda, int m0,
    const __half* __restrict__ B, int ldb, int n0, int K, Epi epi)
{
    extern __shared__ char smem[];
    constexpr int ASZ = TM * ROWB, BSZ = TN * ROWB, STG = ASZ + BSZ;
    constexpr int WM = TM / 4, WN = TN / 2, FM = WM / 16, NF = WN / 8;
    constexpr int GG = (NF > 4) ? 4 : NF;
    const uint32_t s0 = smem_u32(smem);
    const int tid = threadIdx.x, lane = tid & 31, wid = tid >> 5;
    const int wm = wid >> 1, wn = wid & 1;
    const int lrow = lane & 15, lhalf = lane >> 4;
    float acc[FM][NF][4] = {};

    auto issue = [&](int ch, int st) {
        uint32_t d = s0 + st * STG;
        int k0 = ch * 32;
        #pragma unroll
        for (int v = tid; v < TM * 4; v += 256) {
            int row = v >> 2, c = v & 3;
            cpasync16(d + row*ROWB + c*16, A + (m0+row)*lda + k0 + c*8);
        }
        #pragma unroll
        for (int v = tid; v < TN * 4; v += 256) {
            int row = v >> 2, c = v & 3;
            cpasync16(d + ASZ + row*ROWB + c*16, B + (n0+row)*ldb + k0 + c*8);
        }
        CP_COMMIT();
    };

    const int NC = K / 32;
    issue(0, 0);
    for (int ch = 0; ch < NC; ch++) {
        int st = ch & 1;
        if (ch + 1 < NC) { issue(ch + 1, (ch + 1) & 1); CP_WAIT1(); }
        else CP_WAIT0();
        __syncthreads();
        uint32_t d = s0 + st * STG;
        #pragma unroll
        for (int kk = 0; kk < 2; kk++) {
            uint32_t ah[FM][4];
            #pragma unroll
            for (int f = 0; f < FM; f++) {
                uint32_t a = d + (wm*WM + f*16 + lrow)*ROWB + lhalf*16 + kk*32;
                LDSM4(ah[f], a);
            }
            #pragma unroll
            for (int gg = 0; gg < NF; gg += GG) {
                uint32_t bh[GG][2];
                #pragma unroll
                for (int g2 = 0; g2 < GG; g2 += 2) {
                    int g = gg + g2;
                    uint32_t b = d + ASZ + (wn*WN + g*8 + lrow)*ROWB + lhalf*16 + kk*32;
                    uint32_t t4[4];
                    LDSM4(t4, b);
                    bh[g2][0]=t4[0]; bh[g2][1]=t4[2]; bh[g2+1][0]=t4[1]; bh[g2+1][1]=t4[3];
                }
                #pragma unroll
                for (int f = 0; f < FM; f++)
                    #pragma unroll
                    for (int g2 = 0; g2 < GG; g2++)
                        mmaop_h(acc[f][gg+g2], ah[f], bh[g2]);
            }
        }
        __syncthreads();
    }
    #pragma unroll
    for (int f = 0; f < FM; f++)
        #pragma unroll
        for (int g = 0; g < NF; g++) {
            int r = m0 + wm*WM + f*16 + (lane >> 2);
            int c = n0 + wn*WN + g*8 + (lane & 3)*2;
            epi(r,     c, acc[f][g][0], acc[f][g][1]);
            epi(r + 8, c, acc[f][g][2], acc[f][g][3]);
        }
}

// ---- 1-term fp16 GEMM, 3-stage KT=64 (scan) ----
#define ROWC 144
template<int TM, int TN, typename Epi>
__device__ __forceinline__ void gemm1_3s(
    const __half* __restrict__ A, int lda, int m0,
    const __half* __restrict__ B, int ldb, int n0, int K, Epi epi)
{
    extern __shared__ char smem[];
    constexpr int ASZ = TM * ROWC, BSZ = TN * ROWC, STG = ASZ + BSZ;
    constexpr int WM = TM / 4, WN = TN / 2, FM = WM / 16, NF = WN / 8;
    const uint32_t s0 = smem_u32(smem);
    const int tid = threadIdx.x, lane = tid & 31, wid = tid >> 5;
    const int wm = wid >> 1, wn = wid & 1;
    const int lrow = lane & 15, lhalf = lane >> 4;
    float acc[FM][NF][4] = {};

    auto issue = [&](int ch, int st) {
        uint32_t d = s0 + st * STG;
        int k0 = ch * 64;
        #pragma unroll
        for (int v = tid; v < TM * 8; v += 256) {
            int row = v >> 3, c = v & 7;
            cpasync16(d + row*ROWC + c*16, A + (m0+row)*lda + k0 + c*8);
        }
        #pragma unroll
        for (int v = tid; v < TN * 8; v += 256) {
            int row = v >> 3, c = v & 7;
            cpasync16(d + ASZ + row*ROWC + c*16, B + (n0+row)*ldb + k0 + c*8);
        }
        CP_COMMIT();
    };

    const int NC = K / 64;
    issue(0, 0);
    issue(1, 1);
    for (int ch = 0; ch < NC; ch++) {
        if (ch + 2 < NC) { issue(ch + 2, (ch + 2) % 3); CP_WAIT2(); }
        else if (ch + 1 < NC) CP_WAIT1();
        else CP_WAIT0();
        __syncthreads();
        uint32_t d = s0 + (ch % 3) * STG;
        #pragma unroll
        for (int kk = 0; kk < 4; kk++) {
            uint32_t ah[FM][4], bh[NF][2];
            #pragma unroll
            for (int f = 0; f < FM; f++) {
                uint32_t a = d + (wm*WM + f*16 + lrow)*ROWC + lhalf*16 + kk*32;
                LDSM4(ah[f], a);
            }
            #pragma unroll
            for (int g = 0; g < NF; g += 2) {
                uint32_t b = d + ASZ + (wn*WN + g*8 + lrow)*ROWC + lhalf*16 + kk*32;
                uint32_t t4[4];
                LDSM4(t4, b);
                bh[g][0]=t4[0]; bh[g][1]=t4[2]; bh[g+1][0]=t4[1]; bh[g+1][1]=t4[3];
            }
            #pragma unroll
            for (int f = 0; f < FM; f++)
                #pragma unroll
                for (int g = 0; g < NF; g++)
                    mmaop_h(acc[f][g], ah[f], bh[g]);
        }
        __syncthreads();
    }
    #pragma unroll
    for (int f = 0; f < FM; f++)
        #pragma unroll
        for (int g = 0; g < NF; g++) {
            int r = m0 + wm*WM + f*16 + (lane >> 2);
            int c = n0 + wn*WN + g*8 + (lane & 3)*2;
            epi(r,     c, acc[f][g][0], acc[f][g][1]);
            epi(r + 8, c, acc[f][g][2], acc[f][g][3]);
        }
}
#define SMEM_S  (2 * (2*64*ROWB + 2*32*ROWB))      // 30720 (init 3-term)
#define S1_3    (3 * (64*ROWC + 32*ROWC))          // 41472 (scan 1-term 3-stage)
#define S1_2    (2 * (128*ROWB + 128*ROWB))        // 40960 (xpre/logits 1-term)

// ---- prepack ----
__global__ __launch_bounds__(256) void pk_T(const float* __restrict__ src,
                                            bf16* __restrict__ dh, bf16* __restrict__ dl,
                                            int K, int N)
{
    __shared__ float tile[32][33];
    int kb = blockIdx.y * 32, nb = blockIdx.x * 32;
    int tx = threadIdx.x & 31, ty = threadIdx.x >> 5;
    for (int i = ty; i < 32; i += 8)
        tile[i][tx] = src[(kb + i) * N + nb + tx];
    __syncthreads();
    for (int i = ty; i < 32; i += 8) {
        int n = nb + i, k = kb + tx;
        float x = tile[tx][i];
        bf16 h = __float2bfloat16(x);
        dh[n * K + k] = h;
        dl[n * K + k] = __float2bfloat16(x - __bfloat162float(h));
    }
}
__global__ __launch_bounds__(256) void pk_gruH(const float* __restrict__ Wu,
                                               const float* __restrict__ Wr,
                                               const float* __restrict__ Wc)
{
    __shared__ float tile[32][33];
    int z = blockIdx.z;
    int gate = (z < 3) ? z : z - 3, layer = z / 3;
    const float* src = ((gate == 0) ? Wu : (gate == 1) ? Wr : Wc) + layer * 1024 * Hh;
    int kb = blockIdx.y * 32, nb = blockIdx.x * 32;
    int tx = threadIdx.x & 31, ty = threadIdx.x >> 5;
    for (int i = ty; i < 32; i += 8)
        tile[i][tx] = src[(kb + i) * Hh + nb + tx];
    __syncthreads();
    for (int i = ty; i < 32; i += 8)
        g_WgruH[z*SZGRU + (nb + i) * 1024 + kb + tx] = __float2half_rn(tile[tx][i]);
}
__global__ __launch_bounds__(256) void pk_Wo(const float* __restrict__ src)
{
    __shared__ float tile[32][33];
    int kb = blockIdx.y * 32, nb = blockIdx.x * 32;
    int tx = threadIdx.x & 31, ty = threadIdx.x >> 5;
    for (int i = ty; i < 32; i += 8) {
        int n = nb + tx;
        tile[i][tx] = (n < Vv) ? src[(kb + i) * Vv + n] : 0.f;
    }
    __syncthreads();
    for (int i = ty; i < 32; i += 8)
        g_WoH[(nb + i) * Hh + kb + tx] = __float2half_rn(tile[tx][i]);
}
__global__ __launch_bounds__(256) void pk_vgg(const float* __restrict__ src)
{
    int i = (blockIdx.x * 256 + threadIdx.x) * 2;
    sp2(g_vgg_h, g_vgg_l, i, src[i], src[i + 1]);
}
__global__ __launch_bounds__(256) void k_gather(const float* __restrict__ emb,
                                                const int* __restrict__ tok)
{
    int idx = (blockIdx.x * 256 + threadIdx.x) * 2;
    int r = idx >> 9, e = idx & 511;
    int token = tok[(r & 127) * Tt + (r >> 7)];
    sph(g_xembH, idx, emb[token * Hh + e], emb[token * Hh + e + 1]);
}

// ---- init: split-K partials then finalize ----
__global__ __launch_bounds__(256, 1) void k_initp()
{
    int cta = blockIdx.x;
    int ks = cta >> 5, mt = (cta >> 4) & 1, nt = cta & 15;
    int koff = ks * 1024;
    float* out = g_ipart[ks];
    mma_gemm<64,32>(g_vgg_h + koff, g_vgg_l + koff, Ff, mt*64,
                    g_Win_h + koff, g_Win_l + koff, Ff, nt*32, 1024,
        [&](int r, int c, float v0, float v1) {
            out[r*Hh + c] = v0; out[r*Hh + c + 1] = v1;
        });
}
__global__ __launch_bounds__(256) void k_initf(const float* __restrict__ b_in)
{
    int i = (blockIdx.x * 256 + threadIdx.x) * 2;
    float v0 = tanhf(g_ipart[0][i] + g_ipart[1][i] + g_ipart[2][i] + g_ipart[3][i]
                     + b_in[i & 511]);
    float v1 = tanhf(g_ipart[0][i+1] + g_ipart[1][i+1] + g_ipart[2][i+1] + g_ipart[3][i+1]
                     + b_in[(i+1) & 511]);
    g_h0f[i] = v0; g_h0f[i+1] = v1;
    g_h1f[i] = v0; g_h1f[i+1] = v1;
    sph(g_h0H, i, v0, v1);
    int ci = (i >> 9) * 1024 + 512 + (i & 511);
    sph(g_c1H, ci, v0, v1);
}

// ---- layer0 x-projections for all t (128x128, 1-term fp16) ----
__global__ __launch_bounds__(256, 2) void k_xpre(const float* __restrict__ bu,
                                                 const float* __restrict__ br,
                                                 const float* __restrict__ bc)
{
    int n0 = blockIdx.x * 128, m0 = blockIdx.y * 128, gate = blockIdx.z;
    const float* bi = (gate == 0) ? bu : (gate == 1) ? br : bc;
    float* out = (gate == 0) ? g_Xu0 : (gate == 1) ? g_Xr0 : g_Xc0;
    gemm1_2s<128,128>(g_xembH, Hh, m0, g_WgruH + gate*SZGRU, 1024, n0, Hh,
        [&](int r, int c, float v0, float v1) {
            float2 val = make_float2(v0 + bi[c], v1 + bi[c + 1]);
            *(float2*)&out[r*Hh + c] = val;
        });
}

// ---- wave UR ----
__global__ __launch_bounds__(256, 1) void k_ur(int w,
                                               const float* __restrict__ bu1,
                                               const float* __restrict__ br1)
{
    int nt = blockIdx.x, mt = blockIdx.y, z = blockIdx.z;
    int n0 = nt * 32;
    if (z < 2) {
        if (w >= Tt) return;
        int gate = z;
        const float* X = (gate ? g_Xr0 : g_Xu0) + w * BH;
        gemm1_3s<64,32>(g_h0H, Hh, mt*64,
            g_WgruH + gate*SZGRU + 512, 1024, n0, Hh,
            [&](int r, int c, float v0, float v1) {
                int idx = r*Hh + c;
                float s0 = sigmoidf_(v0 + X[idx]);
                float s1 = sigmoidf_(v1 + X[idx+1]);
                if (gate == 0) { g_u0f[idx] = s0; g_u0f[idx+1] = s1; }
                else sph(g_rh0H, idx, s0*g_h0f[idx], s1*g_h0f[idx+1]);
            });
    } else {
        if (w == 0) return;
        int gate = z - 2, par = (w - 1) & 1;
        const float* bi = gate ? br1 : bu1;
        gemm1_3s<64,32>(g_c1H, 1024, mt*64,
            g_WgruH + (3+gate)*SZGRU, 1024, n0, 1024,
            [&](int r, int c, float v0, float v1) {
                int idx = r*Hh + c;
                float s0 = sigmoidf_(v0 + bi[c]);
                float s1 = sigmoidf_(v1 + bi[c+1]);
                if (gate == 0) { g_u1f[idx] = s0; g_u1f[idx+1] = s1; }
                else sph(g_c2H[par], r*1024 + 512 + c,
                         s0*g_h1f[idx], s1*g_h1f[idx+1]);
            });
    }
}

// ---- wave C ----
__global__ __launch_bounds__(256, 1) void k_c(int w, const float* __restrict__ bc1)
{
    int nt = blockIdx.x, mt = blockIdx.y, z = blockIdx.z;
    int n0 = nt * 32;
    if (z == 0) {
        if (w >= Tt) return;
        int par = w & 1;
        const float* Xc = g_Xc0 + w * BH;
        gemm1_3s<64,32>(g_rh0H, Hh, mt*64,
            g_WgruH + 2*SZGRU + 512, 1024, n0, Hh,
            [&](int r, int c, float v0, float v1) {
                int idx = r*Hh + c;
                float c0 = tanhf(v0 + Xc[idx]), c1 = tanhf(v1 + Xc[idx+1]);
                float u0 = g_u0f[idx], u1 = g_u0f[idx+1];
                float h0 = u0*g_h0f[idx]   + (1.f-u0)*c0;
                float h1 = u1*g_h0f[idx+1] + (1.f-u1)*c1;
                g_h0f[idx] = h0; g_h0f[idx+1] = h1;
                sph(g_h0H, idx, h0, h1);
                int ci = r*1024 + c;
                sph(g_c1H, ci, h0, h1);
                sph(g_c2H[par], ci, h0, h1);
            });
    } else {
        if (w == 0) return;
        int par = (w - 1) & 1;
        gemm1_3s<64,32>(g_c2H[par], 1024, mt*64,
            g_WgruH + 5*SZGRU, 1024, n0, 1024,
            [&](int r, int c, float v0, float v1) {
                int idx = r*Hh + c;
                float c0 = tanhf(v0 + bc1[c]), c1 = tanhf(v1 + bc1[c+1]);
                float u0 = g_u1f[idx], u1 = g_u1f[idx+1];
                float h0 = u0*g_h1f[idx]   + (1.f-u0)*c0;
                float h1 = u1*g_h1f[idx+1] + (1.f-u1)*c1;
                g_h1f[idx] = h0; g_h1f[idx+1] = h1;
                sph(g_c1H, r*1024 + 512 + c, h0, h1);
                sph(g_X1ah, ((w-1)*Bb + r)*Hh + c, h0, h1);
            });
    }
}

// ---- logits slab for one timestep t: rows [t*128, t*128+128) of X1 ----
__global__ __launch_bounds__(256, 2) void k_logits_t(int t,
                                                     const float* __restrict__ bout,
                                                     float* __restrict__ out)
{
    int n0 = blockIdx.x * 128, m0 = t * 128;
    gemm1_2s<128,128>(g_X1ah, Hh, m0, g_WoH, Hh, n0, Hh,
        [&](int r, int c, float v0, float v1) {
            if (c < Vv) {
                int b = r & 127;     // r = t*128 + b
                long long base = (long long)(b * Tt + t) * Vv;
                out[base + c] = v0 + bout[c];
                if (c + 1 < Vv) out[base + c + 1] = v1 + bout[c + 1];
            }
        });
}

__global__ __launch_bounds__(256) void k_final(float* __restrict__ out)
{
    int i = blockIdx.x * 256 + threadIdx.x;
    out[(long long)Bb * Tt * Vv + i] = (i >> 16) ? g_h1f[i & (BH-1)] : g_h0f[i & (BH-1)];
}

// ---- launch ----
extern "C" void kernel_launch(void* const* d_in, const int* in_sizes, int n_in,
                              void* d_out, int out_size)
{
    const float* vgg   = (const float*)d_in[0];
    const int*   xTok  = (const int*)  d_in[1];
    const float* emb   = (const float*)d_in[2];
    const float* W_in  = (const float*)d_in[3];
    const float* b_in  = (const float*)d_in[4];
    const float* Wu    = (const float*)d_in[5];
    const float* bu    = (const float*)d_in[6];
    const float* Wr    = (const float*)d_in[7];
    const float* br    = (const float*)d_in[8];
    const float* Wc    = (const float*)d_in[9];
    const float* bc    = (const float*)d_in[10];
    const float* W_out = (const float*)d_in[11];
    const float* b_out = (const float*)d_in[12];
    float* out = (float*)d_out;

    // One-time infra (created on the first, non-captured correctness call).
    static cudaStream_t s2 = nullptr;
    static cudaEvent_t evFork, evDone, evW[Tt + 1];
    if (s2 == nullptr) {
        cudaStreamCreateWithFlags(&s2, cudaStreamNonBlocking);
        cudaEventCreateWithFlags(&evFork, cudaEventDisableTiming);
        cudaEventCreateWithFlags(&evDone, cudaEventDisableTiming);
        for (int i = 0; i <= Tt; i++)
            cudaEventCreateWithFlags(&evW[i], cudaEventDisableTiming);
    }

    cudaFuncSetAttribute(k_xpre,     cudaFuncAttributeMaxDynamicSharedMemorySize, S1_2);
    cudaFuncSetAttribute(k_logits_t, cudaFuncAttributeMaxDynamicSharedMemorySize, S1_2);
    cudaFuncSetAttribute(k_ur,       cudaFuncAttributeMaxDynamicSharedMemorySize, S1_3);
    cudaFuncSetAttribute(k_c,        cudaFuncAttributeMaxDynamicSharedMemorySize, S1_3);

    bf16 *Wih, *Wil;
    cudaGetSymbolAddress((void**)&Wih, g_Win_h);
    cudaGetSymbolAddress((void**)&Wil, g_Win_l);

    // fork side stream; pk_Wo (needed only by logits) runs there
    cudaEventRecord(evFork, 0);
    cudaStreamWaitEvent(s2, evFork, 0);
    pk_Wo<<<dim3(Vpad/32, 16), 256, 0, s2>>>(W_out);

    // main stream: prepack + init + xpre
    pk_vgg<<<(Bb*Ff/2)/256, 256>>>(vgg);
    pk_T<<<dim3(16, 128), 256>>>(W_in, Wih, Wil, Ff, Hh);
    pk_gruH<<<dim3(16, 32, 6), 256>>>(Wu, Wr, Wc);
    k_initp<<<128, 256, SMEM_S>>>();
    k_initf<<<(BH/2)/256, 256>>>(b_in);
    k_gather<<<(TBH/2)/256, 256>>>(emb, xTok);
    k_xpre<<<dim3(4, Tt*Bb/128, 3), 256, S1_2>>>(bu, br, bc);

    // pipelined scan; logits slab for t=w-1 forked onto s2 after k_c(w)
    for (int w = 0; w <= Tt; w++) {
        k_ur<<<dim3(16, 2, 4), 256, S1_3>>>(w, bu + Hh, br + Hh);
        k_c <<<dim3(16, 2, 2), 256, S1_3>>>(w, bc + Hh);
        if (w >= 1) {
            cudaEventRecord(evW[w], 0);
            cudaStreamWaitEvent(s2, evW[w], 0);
            k_logits_t<<<Vpad/128, 256, S1_2, s2>>>(w - 1, b_out, out);
        }
    }

    // join side stream back into main, then final states
    cudaEventRecord(evDone, s2);
    cudaStreamWaitEvent(0, evDone, 0);
    k_final<<<(2*BH)/256, 256>>>(out);
}

// round 16
// speedup vs baseline: 1.1438x; 1.1438x over previous
#include <cuda_runtime.h>
#include <cuda_bf16.h>
#include <cuda_fp16.h>
#include <math.h>
#include <stdint.h>

#define Bb 128
#define Tt 30
#define Vv 10000
#define Hh 512
#define Ff 4096
#define BH (Bb*Hh)
#define TBH (Tt*Bb*Hh)
#define Vpad 10112
#define SZGRU (512*1024)

typedef __nv_bfloat16 bf16;
typedef __nv_bfloat162 bf162;

__device__ float g_h0f[BH], g_h1f[BH], g_u0f[BH], g_u1f[BH];
__device__ float g_Xu0[TBH], g_Xr0[TBH], g_Xc0[TBH];
__device__ float g_ipart[4][BH];

// bf16 operands (init GEMM only)
__device__ __align__(16) bf16 g_vgg_h[Bb*Ff], g_vgg_l[Bb*Ff];
__device__ __align__(16) bf16 g_Win_h[Hh*Ff], g_Win_l[Hh*Ff];

// fp16 activations
__device__ __align__(16) __half g_xembH[TBH];
__device__ __align__(16) __half g_h0H[BH];
__device__ __align__(16) __half g_rh0H[BH];
__device__ __align__(16) __half g_c1H[Bb*1024];
__device__ __align__(16) __half g_c2H[2][Bb*1024];
__device__ __align__(16) __half g_X1ah[TBH];

// fp16 weights
__device__ __align__(16) __half g_WgruH[6*SZGRU];   // [z][N=512, K=1024]
__device__ __align__(16) __half g_WoH[Vpad*Hh];     // [N, K=512]

__device__ __forceinline__ uint32_t smem_u32(const void* p) {
    uint32_t a;
    asm("{ .reg .u64 t; cvta.to.shared.u64 t, %1; cvt.u32.u64 %0, t; }" : "=r"(a) : "l"(p));
    return a;
}
__device__ __forceinline__ void cpasync16(uint32_t dst, const void* src) {
    asm volatile("cp.async.cg.shared.global [%0], [%1], 16;" :: "r"(dst), "l"(src) : "memory");
}
#define CP_COMMIT() asm volatile("cp.async.commit_group;" ::: "memory")
#define CP_WAIT2()  asm volatile("cp.async.wait_group 2;" ::: "memory")
#define CP_WAIT1()  asm volatile("cp.async.wait_group 1;" ::: "memory")
#define CP_WAIT0()  asm volatile("cp.async.wait_group 0;" ::: "memory")
#define LDSM4(R, addr) \
    asm volatile("ldmatrix.sync.aligned.m8n8.x4.shared.b16 {%0,%1,%2,%3}, [%4];" \
        : "=r"((R)[0]), "=r"((R)[1]), "=r"((R)[2]), "=r"((R)[3]) : "r"(addr))

__device__ __forceinline__ void mmaop(float* c, const uint32_t* a, const uint32_t* b) {
    asm volatile("mma.sync.aligned.m16n8k16.row.col.f32.bf16.bf16.f32 "
        "{%0,%1,%2,%3}, {%4,%5,%6,%7}, {%8,%9}, {%0,%1,%2,%3};"
        : "+f"(c[0]), "+f"(c[1]), "+f"(c[2]), "+f"(c[3])
        : "r"(a[0]), "r"(a[1]), "r"(a[2]), "r"(a[3]), "r"(b[0]), "r"(b[1]));
}
__device__ __forceinline__ void mmaop_h(float* c, const uint32_t* a, const uint32_t* b) {
    asm volatile("mma.sync.aligned.m16n8k16.row.col.f32.f16.f16.f32 "
        "{%0,%1,%2,%3}, {%4,%5,%6,%7}, {%8,%9}, {%0,%1,%2,%3};"
        : "+f"(c[0]), "+f"(c[1]), "+f"(c[2]), "+f"(c[3])
        : "r"(a[0]), "r"(a[1]), "r"(a[2]), "r"(a[3]), "r"(b[0]), "r"(b[1]));
}
__device__ __forceinline__ float sigmoidf_(float x) { return 1.0f / (1.0f + expf(-x)); }
__device__ __forceinline__ void sp2(bf16* H, bf16* L, int i, float a, float b) {
    bf16 ha = __float2bfloat16(a), hb = __float2bfloat16(b);
    bf162 hv; hv.x = ha; hv.y = hb;
    bf162 lv; lv.x = __float2bfloat16(a - __bfloat162float(ha));
    lv.y = __float2bfloat16(b - __bfloat162float(hb));
    *(bf162*)&H[i] = hv; *(bf162*)&L[i] = lv;
}
__device__ __forceinline__ void sph(__half* H, int i, float a, float b) {
    __half2 hv; hv.x = __float2half_rn(a); hv.y = __float2half_rn(b);
    *(__half2*)&H[i] = hv;
}

// ---- split-3 bf16 mma GEMM (init only), 2-stage KT=32 ----
#define ROWB 80
template<int TM, int TN, typename Epi>
__device__ __forceinline__ void mma_gemm(
    const bf16* __restrict__ Ah, const bf16* __restrict__ Al, int lda, int m0,
    const bf16* __restrict__ Bh, const bf16* __restrict__ Bl, int ldb, int n0,
    int K, Epi epi)
{
    extern __shared__ char smem[];
    constexpr int ASZ = TM * ROWB, BSZ = TN * ROWB, STG = 2*ASZ + 2*BSZ;
    constexpr int WM = TM / 4, WN = TN / 2, FM = WM / 16, NF = WN / 8;
    constexpr int GG = (NF > 4) ? 4 : NF;
    const uint32_t s0 = smem_u32(smem);
    const int tid = threadIdx.x, lane = tid & 31, wid = tid >> 5;
    const int wm = wid >> 1, wn = wid & 1;
    const int lrow = lane & 15, lhalf = lane >> 4;
    float acc[FM][NF][4] = {};

    auto issue = [&](int ch, int st) {
        uint32_t d = s0 + st * STG;
        int k0 = ch * 32;
        #pragma unroll
        for (int v = tid; v < TM * 4; v += 256) {
            int row = v >> 2, c = v & 3;
            cpasync16(d + row*ROWB + c*16,       Ah + (m0+row)*lda + k0 + c*8);
            cpasync16(d + ASZ + row*ROWB + c*16, Al + (m0+row)*lda + k0 + c*8);
        }
        #pragma unroll
        for (int v = tid; v < TN * 4; v += 256) {
            int row = v >> 2, c = v & 3;
            cpasync16(d + 2*ASZ + row*ROWB + c*16,       Bh + (n0+row)*ldb + k0 + c*8);
            cpasync16(d + 2*ASZ + BSZ + row*ROWB + c*16, Bl + (n0+row)*ldb + k0 + c*8);
        }
        CP_COMMIT();
    };

    const int NC = K / 32;
    issue(0, 0);
    for (int ch = 0; ch < NC; ch++) {
        int st = ch & 1;
        if (ch + 1 < NC) { issue(ch + 1, (ch + 1) & 1); CP_WAIT1(); }
        else CP_WAIT0();
        __syncthreads();
        uint32_t d = s0 + st * STG;
        #pragma unroll
        for (int kk = 0; kk < 2; kk++) {
            uint32_t ah[FM][4], al[FM][4];
            #pragma unroll
            for (int f = 0; f < FM; f++) {
                uint32_t a = d + (wm*WM + f*16 + lrow)*ROWB + lhalf*16 + kk*32;
                LDSM4(ah[f], a);
                LDSM4(al[f], a + ASZ);
            }
            #pragma unroll
            for (int gg = 0; gg < NF; gg += GG) {
                uint32_t bh[GG][2], bl[GG][2];
                #pragma unroll
                for (int g2 = 0; g2 < GG; g2 += 2) {
                    int g = gg + g2;
                    uint32_t b = d + 2*ASZ + (wn*WN + g*8 + lrow)*ROWB + lhalf*16 + kk*32;
                    uint32_t t4[4];
                    LDSM4(t4, b);
                    bh[g2][0]=t4[0]; bh[g2][1]=t4[2]; bh[g2+1][0]=t4[1]; bh[g2+1][1]=t4[3];
                    LDSM4(t4, b + BSZ);
                    bl[g2][0]=t4[0]; bl[g2][1]=t4[2]; bl[g2+1][0]=t4[1]; bl[g2+1][1]=t4[3];
                }
                #pragma unroll
                for (int f = 0; f < FM; f++)
                    #pragma unroll
                    for (int g2 = 0; g2 < GG; g2++) {
                        mmaop(acc[f][gg+g2], ah[f], bh[g2]);
                        mmaop(acc[f][gg+g2], ah[f], bl[g2]);
                        mmaop(acc[f][gg+g2], al[f], bh[g2]);
                    }
            }
        }
        __syncthreads();
    }
    #pragma unroll
    for (int f = 0; f < FM; f++)
        #pragma unroll
        for (int g = 0; g < NF; g++) {
            int r = m0 + wm*WM + f*16 + (lane >> 2);
            int c = n0 + wn*WN + g*8 + (lane & 3)*2;
            epi(r,     c, acc[f][g][0], acc[f][g][1]);
            epi(r + 8, c, acc[f][g][2], acc[f][g][3]);
        }
}

// ---- 1-term fp16 GEMM, 2-stage KT=32 (xpre / logits) ----
template<int TM, int TN, typename Epi>
__device__ __forceinline__ void gemm1_2s(
    const __half* __restrict__ A, int lda, int m0,
    const __half* __restrict__ B, int ldb, int n0, int K, Epi epi)
{
    extern __shared__ char smem[];
    constexpr int ASZ = TM * ROWB, BSZ = TN * ROWB, STG = ASZ + BSZ;
    constexpr int WM = TM / 4, WN = TN / 2, FM = WM / 16, NF = WN / 8;
    constexpr int GG = (NF > 4) ? 4 : NF;
    const uint32_t s0 = smem_u32(smem);
    const int tid = threadIdx.x, lane = tid & 31, wid = tid >> 5;
    const int wm = wid >> 1, wn = wid & 1;
    const int lrow = lane & 15, lhalf = lane >> 4;
    float acc[FM][NF][4] = {};

    auto issue = [&](int ch, int st) {
        uint32_t d = s0 + st * STG;
        int k0 = ch * 32;
        #pragma unroll
        for (int v = tid; v < TM * 4; v += 256) {
            int row = v >> 2, c = v & 3;
            cpasync16(d + row*ROWB + c*16, A + (m0+row)*lda + k0 + c*8);
        }
        #pragma unroll
        for (int v = tid; v < TN * 4; v += 256) {
            int row = v >> 2, c = v & 3;
            cpasync16(d + ASZ + row*ROWB + c*16, B + (n0+row)*ldb + k0 + c*8);
        }
        CP_COMMIT();
    };

    const int NC = K / 32;
    issue(0, 0);
    for (int ch = 0; ch < NC; ch++) {
        int st = ch & 1;
        if (ch + 1 < NC) { issue(ch + 1, (ch + 1) & 1); CP_WAIT1(); }
        else CP_WAIT0();
        __syncthreads();
        uint32_t d = s0 + st * STG;
        #pragma unroll
        for (int kk = 0; kk < 2; kk++) {
            uint32_t ah[FM][4];
            #pragma unroll
            for (int f = 0; f < FM; f++) {
                uint32_t a = d + (wm*WM + f*16 + lrow)*ROWB + lhalf*16 + kk*32;
                LDSM4(ah[f], a);
            }
            #pragma unroll
            for (int gg = 0; gg < NF; gg += GG) {
                uint32_t bh[GG][2];
                #pragma unroll
                for (int g2 = 0; g2 < GG; g2 += 2) {
                    int g = gg + g2;
                    uint32_t b = d + ASZ + (wn*WN + g*8 + lrow)*ROWB + lhalf*16 + kk*32;
                    uint32_t t4[4];
                    LDSM4(t4, b);
                    bh[g2][0]=t4[0]; bh[g2][1]=t4[2]; bh[g2+1][0]=t4[1]; bh[g2+1][1]=t4[3];
                }
                #pragma unroll
                for (int f = 0; f < FM; f++)
                    #pragma unroll
                    for (int g2 = 0; g2 < GG; g2++)
                        mmaop_h(acc[f][gg+g2], ah[f], bh[g2]);
            }
        }
        __syncthreads();
    }
    #pragma unroll
    for (int f = 0; f < FM; f++)
        #pragma unroll
        for (int g = 0; g < NF; g++) {
            int r = m0 + wm*WM + f*16 + (lane >> 2);
            int c = n0 + wn*WN + g*8 + (lane & 3)*2;
            epi(r,     c, acc[f][g][0], acc[f][g][1]);
            epi(r + 8, c, acc[f][g][2], acc[f][g][3]);
        }
}

// ---- 1-term fp16 GEMM, 3-stage KT=64 (scan) ----
#define ROWC 144
template<int TM, int TN, typename Epi>
__device__ __forceinline__ void gemm1_3s(
    const __half* __restrict__ A, int lda, int m0,
    const __half* __restrict__ B, int ldb, int n0, int K, Epi epi)
{
    extern __shared__ char smem[];
    constexpr int ASZ = TM * ROWC, BSZ = TN * ROWC, STG = ASZ + BSZ;
    constexpr int WM = TM / 4, WN = TN / 2, FM = WM / 16, NF = WN / 8;
    const uint32_t s0 = smem_u32(smem);
    const int tid = threadIdx.x, lane = tid & 31, wid = tid >> 5;
    const int wm = wid >> 1, wn = wid & 1;
    const int lrow = lane & 15, lhalf = lane >> 4;
    float acc[FM][NF][4] = {};

    auto issue = [&](int ch, int st) {
        uint32_t d = s0 + st * STG;
        int k0 = ch * 64;
        #pragma unroll
        for (int v = tid; v < TM * 8; v += 256) {
            int row = v >> 3, c = v & 7;
            cpasync16(d + row*ROWC + c*16, A + (m0+row)*lda + k0 + c*8);
        }
        #pragma unroll
        for (int v = tid; v < TN * 8; v += 256) {
            int row = v >> 3, c = v & 7;
            cpasync16(d + ASZ + row*ROWC + c*16, B + (n0+row)*ldb + k0 + c*8);
        }
        CP_COMMIT();
    };

    const int NC = K / 64;
    issue(0, 0);
    issue(1, 1);
    for (int ch = 0; ch < NC; ch++) {
        if (ch + 2 < NC) { issue(ch + 2, (ch + 2) % 3); CP_WAIT2(); }
        else if (ch + 1 < NC) CP_WAIT1();
        else CP_WAIT0();
        __syncthreads();
        uint32_t d = s0 + (ch % 3) * STG;
        #pragma unroll
        for (int kk = 0; kk < 4; kk++) {
            uint32_t ah[FM][4], bh[NF][2];
            #pragma unroll
            for (int f = 0; f < FM; f++) {
                uint32_t a = d + (wm*WM + f*16 + lrow)*ROWC + lhalf*16 + kk*32;
                LDSM4(ah[f], a);
            }
            #pragma unroll
            for (int g = 0; g < NF; g += 2) {
                uint32_t b = d + ASZ + (wn*WN + g*8 + lrow)*ROWC + lhalf*16 + kk*32;
                uint32_t t4[4];
                LDSM4(t4, b);
                bh[g][0]=t4[0]; bh[g][1]=t4[2]; bh[g+1][0]=t4[1]; bh[g+1][1]=t4[3];
            }
            #pragma unroll
            for (int f = 0; f < FM; f++)
                #pragma unroll
                for (int g = 0; g < NF; g++)
                    mmaop_h(acc[f][g], ah[f], bh[g]);
        }
        __syncthreads();
    }
    #pragma unroll
    for (int f = 0; f < FM; f++)
        #pragma unroll
        for (int g = 0; g < NF; g++) {
            int r = m0 + wm*WM + f*16 + (lane >> 2);
            int c = n0 + wn*WN + g*8 + (lane & 3)*2;
            epi(r,     c, acc[f][g][0], acc[f][g][1]);
            epi(r + 8, c, acc[f][g][2], acc[f][g][3]);
        }
}
#define SMEM_S  (2 * (2*64*ROWB + 2*32*ROWB))      // 30720 (init 3-term)
#define S1_3    (3 * (64*ROWC + 32*ROWC))          // 41472 (scan 1-term 3-stage)
#define S1_2    (2 * (128*ROWB + 128*ROWB))        // 40960 (xpre/logits 1-term)

// ---- prepack ----
__global__ __launch_bounds__(256) void pk_T(const float* __restrict__ src,
                                            bf16* __restrict__ dh, bf16* __restrict__ dl,
                                            int K, int N)
{
    __shared__ float tile[32][33];
    int kb = blockIdx.y * 32, nb = blockIdx.x * 32;
    int tx = threadIdx.x & 31, ty = threadIdx.x >> 5;
    for (int i = ty; i < 32; i += 8)
        tile[i][tx] = src[(kb + i) * N + nb + tx];
    __syncthreads();
    for (int i = ty; i < 32; i += 8) {
        int n = nb + i, k = kb + tx;
        float x = tile[tx][i];
        bf16 h = __float2bfloat16(x);
        dh[n * K + k] = h;
        dl[n * K + k] = __float2bfloat16(x - __bfloat162float(h));
    }
}
__global__ __launch_bounds__(256) void pk_gruH(const float* __restrict__ Wu,
                                               const float* __restrict__ Wr,
                                               const float* __restrict__ Wc)
{
    __shared__ float tile[32][33];
    int z = blockIdx.z;
    int gate = (z < 3) ? z : z - 3, layer = z / 3;
    const float* src = ((gate == 0) ? Wu : (gate == 1) ? Wr : Wc) + layer * 1024 * Hh;
    int kb = blockIdx.y * 32, nb = blockIdx.x * 32;
    int tx = threadIdx.x & 31, ty = threadIdx.x >> 5;
    for (int i = ty; i < 32; i += 8)
        tile[i][tx] = src[(kb + i) * Hh + nb + tx];
    __syncthreads();
    for (int i = ty; i < 32; i += 8)
        g_WgruH[z*SZGRU + (nb + i) * 1024 + kb + tx] = __float2half_rn(tile[tx][i]);
}
__global__ __launch_bounds__(256) void pk_Wo(const float* __restrict__ src)
{
    __shared__ float tile[32][33];
    int kb = blockIdx.y * 32, nb = blockIdx.x * 32;
    int tx = threadIdx.x & 31, ty = threadIdx.x >> 5;
    for (int i = ty; i < 32; i += 8) {
        int n = nb + tx;
        tile[i][tx] = (n < Vv) ? src[(kb + i) * Vv + n] : 0.f;
    }
    __syncthreads();
    for (int i = ty; i < 32; i += 8)
        g_WoH[(nb + i) * Hh + kb + tx] = __float2half_rn(tile[tx][i]);
}
__global__ __launch_bounds__(256) void pk_vgg(const float* __restrict__ src)
{
    int i = (blockIdx.x * 256 + threadIdx.x) * 2;
    sp2(g_vgg_h, g_vgg_l, i, src[i], src[i + 1]);
}
__global__ __launch_bounds__(256) void k_gather(const float* __restrict__ emb,
                                                const int* __restrict__ tok)
{
    int idx = (blockIdx.x * 256 + threadIdx.x) * 2;
    int r = idx >> 9, e = idx & 511;
    int token = tok[(r & 127) * Tt + (r >> 7)];
    sph(g_xembH, idx, emb[token * Hh + e], emb[token * Hh + e + 1]);
}

// ---- init: split-K partials then finalize ----
__global__ __launch_bounds__(256, 1) void k_initp()
{
    int cta = blockIdx.x;
    int ks = cta >> 5, mt = (cta >> 4) & 1, nt = cta & 15;
    int koff = ks * 1024;
    float* out = g_ipart[ks];
    mma_gemm<64,32>(g_vgg_h + koff, g_vgg_l + koff, Ff, mt*64,
                    g_Win_h + koff, g_Win_l + koff, Ff, nt*32, 1024,
        [&](int r, int c, float v0, float v1) {
            out[r*Hh + c] = v0; out[r*Hh + c + 1] = v1;
        });
}
__global__ __launch_bounds__(256) void k_initf(const float* __restrict__ b_in)
{
    int i = (blockIdx.x * 256 + threadIdx.x) * 2;
    float v0 = tanhf(g_ipart[0][i] + g_ipart[1][i] + g_ipart[2][i] + g_ipart[3][i]
                     + b_in[i & 511]);
    float v1 = tanhf(g_ipart[0][i+1] + g_ipart[1][i+1] + g_ipart[2][i+1] + g_ipart[3][i+1]
                     + b_in[(i+1) & 511]);
    g_h0f[i] = v0; g_h0f[i+1] = v1;
    g_h1f[i] = v0; g_h1f[i+1] = v1;
    sph(g_h0H, i, v0, v1);
    int ci = (i >> 9) * 1024 + 512 + (i & 511);
    sph(g_c1H, ci, v0, v1);
}

// ---- layer0 x-projections for all t (128x128, 1-term fp16) ----
__global__ __launch_bounds__(256, 2) void k_xpre(const float* __restrict__ bu,
                                                 const float* __restrict__ br,
                                                 const float* __restrict__ bc)
{
    int n0 = blockIdx.x * 128, m0 = blockIdx.y * 128, gate = blockIdx.z;
    const float* bi = (gate == 0) ? bu : (gate == 1) ? br : bc;
    float* out = (gate == 0) ? g_Xu0 : (gate == 1) ? g_Xr0 : g_Xc0;
    gemm1_2s<128,128>(g_xembH, Hh, m0, g_WgruH + gate*SZGRU, 1024, n0, Hh,
        [&](int r, int c, float v0, float v1) {
            float2 val = make_float2(v0 + bi[c], v1 + bi[c + 1]);
            *(float2*)&out[r*Hh + c] = val;
        });
}

// ---- wave UR ----
__global__ __launch_bounds__(256, 1) void k_ur(int w,
                                               const float* __restrict__ bu1,
                                               const float* __restrict__ br1)
{
    int nt = blockIdx.x, mt = blockIdx.y, z = blockIdx.z;
    int n0 = nt * 32;
    if (z < 2) {
        if (w >= Tt) return;
        int gate = z;
        const float* X = (gate ? g_Xr0 : g_Xu0) + w * BH;
        gemm1_3s<64,32>(g_h0H, Hh, mt*64,
            g_WgruH + gate*SZGRU + 512, 1024, n0, Hh,
            [&](int r, int c, float v0, float v1) {
                int idx = r*Hh + c;
                float s0 = sigmoidf_(v0 + X[idx]);
                float s1 = sigmoidf_(v1 + X[idx+1]);
                if (gate == 0) { g_u0f[idx] = s0; g_u0f[idx+1] = s1; }
                else sph(g_rh0H, idx, s0*g_h0f[idx], s1*g_h0f[idx+1]);
            });
    } else {
        if (w == 0) return;
        int gate = z - 2, par = (w - 1) & 1;
        const float* bi = gate ? br1 : bu1;
        gemm1_3s<64,32>(g_c1H, 1024, mt*64,
            g_WgruH + (3+gate)*SZGRU, 1024, n0, 1024,
            [&](int r, int c, float v0, float v1) {
                int idx = r*Hh + c;
                float s0 = sigmoidf_(v0 + bi[c]);
                float s1 = sigmoidf_(v1 + bi[c+1]);
                if (gate == 0) { g_u1f[idx] = s0; g_u1f[idx+1] = s1; }
                else sph(g_c2H[par], r*1024 + 512 + c,
                         s0*g_h1f[idx], s1*g_h1f[idx+1]);
            });
    }
}

// ---- wave C ----
__global__ __launch_bounds__(256, 1) void k_c(int w, const float* __restrict__ bc1)
{
    int nt = blockIdx.x, mt = blockIdx.y, z = blockIdx.z;
    int n0 = nt * 32;
    if (z == 0) {
        if (w >= Tt) return;
        int par = w & 1;
        const float* Xc = g_Xc0 + w * BH;
        gemm1_3s<64,32>(g_rh0H, Hh, mt*64,
            g_WgruH + 2*SZGRU + 512, 1024, n0, Hh,
            [&](int r, int c, float v0, float v1) {
                int idx = r*Hh + c;
                float c0 = tanhf(v0 + Xc[idx]), c1 = tanhf(v1 + Xc[idx+1]);
                float u0 = g_u0f[idx], u1 = g_u0f[idx+1];
                float h0 = u0*g_h0f[idx]   + (1.f-u0)*c0;
                float h1 = u1*g_h0f[idx+1] + (1.f-u1)*c1;
                g_h0f[idx] = h0; g_h0f[idx+1] = h1;
                sph(g_h0H, idx, h0, h1);
                int ci = r*1024 + c;
                sph(g_c1H, ci, h0, h1);
                sph(g_c2H[par], ci, h0, h1);
            });
    } else {
        if (w == 0) return;
        int par = (w - 1) & 1;
        gemm1_3s<64,32>(g_c2H[par], 1024, mt*64,
            g_WgruH + 5*SZGRU, 1024, n0, 1024,
            [&](int r, int c, float v0, float v1) {
                int idx = r*Hh + c;
                float c0 = tanhf(v0 + bc1[c]), c1 = tanhf(v1 + bc1[c+1]);
                float u0 = g_u1f[idx], u1 = g_u1f[idx+1];
                float h0 = u0*g_h1f[idx]   + (1.f-u0)*c0;
                float h1 = u1*g_h1f[idx+1] + (1.f-u1)*c1;
                g_h1f[idx] = h0; g_h1f[idx+1] = h1;
                sph(g_c1H, r*1024 + 512 + c, h0, h1);
                sph(g_X1ah, ((w-1)*Bb + r)*Hh + c, h0, h1);
            });
    }
}

// ---- logits: 1-term fp16 ----
__global__ __launch_bounds__(256, 2) void k_logits(const float* __restrict__ bout,
                                                   float* __restrict__ out)
{
    int n0 = blockIdx.x * 128, m0 = blockIdx.y * 128;
    gemm1_2s<128,128>(g_X1ah, Hh, m0, g_WoH, Hh, n0, Hh,
        [&](int r, int c, float v0, float v1) {
            if (c < Vv) {
                int t = r >> 7, b = r & 127;
                long long base = (long long)(b * Tt + t) * Vv;
                out[base + c] = v0 + bout[c];
                if (c + 1 < Vv) out[base + c + 1] = v1 + bout[c + 1];
            }
        });
}

__global__ __launch_bounds__(256) void k_final(float* __restrict__ out)
{
    int i = blockIdx.x * 256 + threadIdx.x;
    out[(long long)Bb * Tt * Vv + i] = (i >> 16) ? g_h1f[i & (BH-1)] : g_h0f[i & (BH-1)];
}

// ---- launch ----
extern "C" void kernel_launch(void* const* d_in, const int* in_sizes, int n_in,
                              void* d_out, int out_size)
{
    const float* vgg   = (const float*)d_in[0];
    const int*   xTok  = (const int*)  d_in[1];
    const float* emb   = (const float*)d_in[2];
    const float* W_in  = (const float*)d_in[3];
    const float* b_in  = (const float*)d_in[4];
    const float* Wu    = (const float*)d_in[5];
    const float* bu    = (const float*)d_in[6];
    const float* Wr    = (const float*)d_in[7];
    const float* br    = (const float*)d_in[8];
    const float* Wc    = (const float*)d_in[9];
    const float* bc    = (const float*)d_in[10];
    const float* W_out = (const float*)d_in[11];
    const float* b_out = (const float*)d_in[12];
    float* out = (float*)d_out;

    // One-time infra (created on first, non-captured correctness call).
    static cudaStream_t s2 = nullptr;
    static cudaEvent_t evFork, evB, evScan, evFin;
    if (s2 == nullptr) {
        cudaStreamCreateWithFlags(&s2, cudaStreamNonBlocking);
        cudaEventCreateWithFlags(&evFork, cudaEventDisableTiming);
        cudaEventCreateWithFlags(&evB,    cudaEventDisableTiming);
        cudaEventCreateWithFlags(&evScan, cudaEventDisableTiming);
        cudaEventCreateWithFlags(&evFin,  cudaEventDisableTiming);
    }

    cudaFuncSetAttribute(k_xpre,   cudaFuncAttributeMaxDynamicSharedMemorySize, S1_2);
    cudaFuncSetAttribute(k_logits, cudaFuncAttributeMaxDynamicSharedMemorySize, S1_2);
    cudaFuncSetAttribute(k_ur,     cudaFuncAttributeMaxDynamicSharedMemorySize, S1_3);
    cudaFuncSetAttribute(k_c,      cudaFuncAttributeMaxDynamicSharedMemorySize, S1_3);

    bf16 *Wih, *Wil;
    cudaGetSymbolAddress((void**)&Wih, g_Win_h);
    cudaGetSymbolAddress((void**)&Wil, g_Win_l);

    // fork: chain B (GRU weights + gather + xpre) and pk_Wo on side stream
    cudaEventRecord(evFork, 0);
    cudaStreamWaitEvent(s2, evFork, 0);
    pk_gruH<<<dim3(16, 32, 6), 256, 0, s2>>>(Wu, Wr, Wc);
    k_gather<<<(TBH/2)/256, 256, 0, s2>>>(emb, xTok);
    k_xpre<<<dim3(4, Tt*Bb/128, 3), 256, S1_2, s2>>>(bu, br, bc);
    pk_Wo<<<dim3(Vpad/32, 16), 256, 0, s2>>>(W_out);

    // chain A on main: vgg prepack + init hidden state
    pk_vgg<<<(Bb*Ff/2)/256, 256>>>(vgg);
    pk_T<<<dim3(16, 128), 256>>>(W_in, Wih, Wil, Ff, Hh);
    k_initp<<<128, 256, SMEM_S>>>();
    k_initf<<<(BH/2)/256, 256>>>(b_in);

    // join B before scan (scan needs xpre outputs + h0H)
    cudaEventRecord(evB, s2);
    cudaStreamWaitEvent(0, evB, 0);

    // pipelined wavefront scan (main stream only — no concurrent work)
    for (int w = 0; w <= Tt; w++) {
        k_ur<<<dim3(16, 2, 4), 256, S1_3>>>(w, bu + Hh, br + Hh);
        k_c <<<dim3(16, 2, 2), 256, S1_3>>>(w, bc + Hh);
    }

    // k_final on side stream concurrent with logits (disjoint output regions)
    cudaEventRecord(evScan, 0);
    cudaStreamWaitEvent(s2, evScan, 0);
    k_final<<<(2*BH)/256, 256, 0, s2>>>(out);

    k_logits<<<dim3(Vpad/128, Tt*Bb/128), 256, S1_2>>>(b_out, out);

    cudaEventRecord(evFin, s2);
    cudaStreamWaitEvent(0, evFin, 0);
}

// round 17
// speedup vs baseline: 1.1807x; 1.0323x over previous
#include <cuda_runtime.h>
#include <cuda_bf16.h>
#include <cuda_fp16.h>
#include <math.h>
#include <stdint.h>

#define Bb 128
#define Tt 30
#define Vv 10000
#define Hh 512
#define Ff 4096
#define BH (Bb*Hh)
#define TBH (Tt*Bb*Hh)
#define Vpad 10112
#define SZGRU (512*1024)

typedef __nv_bfloat16 bf16;
typedef __nv_bfloat162 bf162;

__device__ float g_h0f[BH], g_h1f[BH], g_u0f[BH], g_u1f[BH];
__device__ float g_Xu0[TBH], g_Xr0[TBH], g_Xc0[TBH];
__device__ float g_ipart[4][BH];
__device__ unsigned g_cnt;

// bf16 operands (init GEMM only)
__device__ __align__(16) bf16 g_vgg_h[Bb*Ff], g_vgg_l[Bb*Ff];
__device__ __align__(16) bf16 g_Win_h[Hh*Ff], g_Win_l[Hh*Ff];

// fp16 activations
__device__ __align__(16) __half g_xembH[TBH];
__device__ __align__(16) __half g_h0H[BH];
__device__ __align__(16) __half g_rh0H[BH];
__device__ __align__(16) __half g_c1H[Bb*1024];
__device__ __align__(16) __half g_c2H[2][Bb*1024];
__device__ __align__(16) __half g_X1ah[TBH];

// fp16 weights
__device__ __align__(16) __half g_WgruH[6*SZGRU];   // [z][N=512, K=1024]
__device__ __align__(16) __half g_WoH[Vpad*Hh];     // [N, K=512]

__device__ __forceinline__ uint32_t smem_u32(const void* p) {
    uint32_t a;
    asm("{ .reg .u64 t; cvta.to.shared.u64 t, %1; cvt.u32.u64 %0, t; }" : "=r"(a) : "l"(p));
    return a;
}
__device__ __forceinline__ void cpasync16(uint32_t dst, const void* src) {
    asm volatile("cp.async.cg.shared.global [%0], [%1], 16;" :: "r"(dst), "l"(src) : "memory");
}
#define CP_COMMIT() asm volatile("cp.async.commit_group;" ::: "memory")
#define CP_WAIT2()  asm volatile("cp.async.wait_group 2;" ::: "memory")
#define CP_WAIT1()  asm volatile("cp.async.wait_group 1;" ::: "memory")
#define CP_WAIT0()  asm volatile("cp.async.wait_group 0;" ::: "memory")
#define LDSM4(R, addr) \
    asm volatile("ldmatrix.sync.aligned.m8n8.x4.shared.b16 {%0,%1,%2,%3}, [%4];" \
        : "=r"((R)[0]), "=r"((R)[1]), "=r"((R)[2]), "=r"((R)[3]) : "r"(addr))

__device__ __forceinline__ void mmaop(float* c, const uint32_t* a, const uint32_t* b) {
    asm volatile("mma.sync.aligned.m16n8k16.row.col.f32.bf16.bf16.f32 "
        "{%0,%1,%2,%3}, {%4,%5,%6,%7}, {%8,%9}, {%0,%1,%2,%3};"
        : "+f"(c[0]), "+f"(c[1]), "+f"(c[2]), "+f"(c[3])
        : "r"(a[0]), "r"(a[1]), "r"(a[2]), "r"(a[3]), "r"(b[0]), "r"(b[1]));
}
__device__ __forceinline__ void mmaop_h(float* c, const uint32_t* a, const uint32_t* b) {
    asm volatile("mma.sync.aligned.m16n8k16.row.col.f32.f16.f16.f32 "
        "{%0,%1,%2,%3}, {%4,%5,%6,%7}, {%8,%9}, {%0,%1,%2,%3};"
        : "+f"(c[0]), "+f"(c[1]), "+f"(c[2]), "+f"(c[3])
        : "r"(a[0]), "r"(a[1]), "r"(a[2]), "r"(a[3]), "r"(b[0]), "r"(b[1]));
}
__device__ __forceinline__ float sigmoidf_(float x) { return 1.0f / (1.0f + expf(-x)); }
__device__ __forceinline__ void sp2(bf16* H, bf16* L, int i, float a, float b) {
    bf16 ha = __float2bfloat16(a), hb = __float2bfloat16(b);
    bf162 hv; hv.x = ha; hv.y = hb;
    bf162 lv; lv.x = __float2bfloat16(a - __bfloat162float(ha));
    lv.y = __float2bfloat16(b - __bfloat162float(hb));
    *(bf162*)&H[i] = hv; *(bf162*)&L[i] = lv;
}
__device__ __forceinline__ void sph(__half* H, int i, float a, float b) {
    __half2 hv; hv.x = __float2half_rn(a); hv.y = __float2half_rn(b);
    *(__half2*)&H[i] = hv;
}

// ---- grid barrier (cooperative launch => co-resident). Monotonic counter. ----
__device__ __forceinline__ void gbar(unsigned target) {
    __syncthreads();
    if (threadIdx.x == 0) {
        __threadfence();
        atomicAdd(&g_cnt, 1u);
        unsigned cur;
        do {
            asm volatile("ld.acquire.gpu.global.u32 %0, [%1];" : "=r"(cur) : "l"(&g_cnt));
            if (cur < target) __nanosleep(32);
        } while (cur < target);
    }
    __syncthreads();
}

// ---- split-3 bf16 mma GEMM (init only), 2-stage KT=32 ----
#define ROWB 80
template<int TM, int TN, typename Epi>
__device__ __forceinline__ void mma_gemm(
    const bf16* __restrict__ Ah, const bf16* __restrict__ Al, int lda, int m0,
    const bf16* __restrict__ Bh, const bf16* __restrict__ Bl, int ldb, int n0,
    int K, Epi epi)
{
    extern __shared__ char smem[];
    constexpr int ASZ = TM * ROWB, BSZ = TN * ROWB, STG = 2*ASZ + 2*BSZ;
    constexpr int WM = TM / 4, WN = TN / 2, FM = WM / 16, NF = WN / 8;
    constexpr int GG = (NF > 4) ? 4 : NF;
    const uint32_t s0 = smem_u32(smem);
    const int tid = threadIdx.x, lane = tid & 31, wid = tid >> 5;
    const int wm = wid >> 1, wn = wid & 1;
    const int lrow = lane & 15, lhalf = lane >> 4;
    float acc[FM][NF][4] = {};

    auto issue = [&](int ch, int st) {
        uint32_t d = s0 + st * STG;
        int k0 = ch * 32;
        #pragma unroll
        for (int v = tid; v < TM * 4; v += 256) {
            int row = v >> 2, c = v & 3;
            cpasync16(d + row*ROWB + c*16,       Ah + (m0+row)*lda + k0 + c*8);
            cpasync16(d + ASZ + row*ROWB + c*16, Al + (m0+row)*lda + k0 + c*8);
        }
        #pragma unroll
        for (int v = tid; v < TN * 4; v += 256) {
            int row = v >> 2, c = v & 3;
            cpasync16(d + 2*ASZ + row*ROWB + c*16,       Bh + (n0+row)*ldb + k0 + c*8);
            cpasync16(d + 2*ASZ + BSZ + row*ROWB + c*16, Bl + (n0+row)*ldb + k0 + c*8);
        }
        CP_COMMIT();
    };

    const int NC = K / 32;
    issue(0, 0);
    for (int ch = 0; ch < NC; ch++) {
        int st = ch & 1;
        if (ch + 1 < NC) { issue(ch + 1, (ch + 1) & 1); CP_WAIT1(); }
        else CP_WAIT0();
        __syncthreads();
        uint32_t d = s0 + st * STG;
        #pragma unroll
        for (int kk = 0; kk < 2; kk++) {
            uint32_t ah[FM][4], al[FM][4];
            #pragma unroll
            for (int f = 0; f < FM; f++) {
                uint32_t a = d + (wm*WM + f*16 + lrow)*ROWB + lhalf*16 + kk*32;
                LDSM4(ah[f], a);
                LDSM4(al[f], a + ASZ);
            }
            #pragma unroll
            for (int gg = 0; gg < NF; gg += GG) {
                uint32_t bh[GG][2], bl[GG][2];
                #pragma unroll
                for (int g2 = 0; g2 < GG; g2 += 2) {
                    int g = gg + g2;
                    uint32_t b = d + 2*ASZ + (wn*WN + g*8 + lrow)*ROWB + lhalf*16 + kk*32;
                    uint32_t t4[4];
                    LDSM4(t4, b);
                    bh[g2][0]=t4[0]; bh[g2][1]=t4[2]; bh[g2+1][0]=t4[1]; bh[g2+1][1]=t4[3];
                    LDSM4(t4, b + BSZ);
                    bl[g2][0]=t4[0]; bl[g2][1]=t4[2]; bl[g2+1][0]=t4[1]; bl[g2+1][1]=t4[3];
                }
                #pragma unroll
                for (int f = 0; f < FM; f++)
                    #pragma unroll
                    for (int g2 = 0; g2 < GG; g2++) {
                        mmaop(acc[f][gg+g2], ah[f], bh[g2]);
                        mmaop(acc[f][gg+g2], ah[f], bl[g2]);
                        mmaop(acc[f][gg+g2], al[f], bh[g2]);
                    }
            }
        }
        __syncthreads();
    }
    #pragma unroll
    for (int f = 0; f < FM; f++)
        #pragma unroll
        for (int g = 0; g < NF; g++) {
            int r = m0 + wm*WM + f*16 + (lane >> 2);
            int c = n0 + wn*WN + g*8 + (lane & 3)*2;
            epi(r,     c, acc[f][g][0], acc[f][g][1]);
            epi(r + 8, c, acc[f][g][2], acc[f][g][3]);
        }
}

// ---- 1-term fp16 GEMM, 2-stage KT=32 (xpre / logits) ----
template<int TM, int TN, typename Epi>
__device__ __forceinline__ void gemm1_2s(
    const __half* __restrict__ A, int lda, int m0,
    const __half* __restrict__ B, int ldb, int n0, int K, Epi epi)
{
    extern __shared__ char smem[];
    constexpr int ASZ = TM * ROWB, BSZ = TN * ROWB, STG = ASZ + BSZ;
    constexpr int WM = TM / 4, WN = TN / 2, FM = WM / 16, NF = WN / 8;
    constexpr int GG = (NF > 4) ? 4 : NF;
    const uint32_t s0 = smem_u32(smem);
    const int tid = threadIdx.x, lane = tid & 31, wid = tid >> 5;
    const int wm = wid >> 1, wn = wid & 1;
    const int lrow = lane & 15, lhalf = lane >> 4;
    float acc[FM][NF][4] = {};

    auto issue = [&](int ch, int st) {
        uint32_t d = s0 + st * STG;
        int k0 = ch * 32;
        #pragma unroll
        for (int v = tid; v < TM * 4; v += 256) {
            int row = v >> 2, c = v & 3;
            cpasync16(d + row*ROWB + c*16, A + (m0+row)*lda + k0 + c*8);
        }
        #pragma unroll
        for (int v = tid; v < TN * 4; v += 256) {
            int row = v >> 2, c = v & 3;
            cpasync16(d + ASZ + row*ROWB + c*16, B + (n0+row)*ldb + k0 + c*8);
        }
        CP_COMMIT();
    };

    const int NC = K / 32;
    issue(0, 0);
    for (int ch = 0; ch < NC; ch++) {
        int st = ch & 1;
        if (ch + 1 < NC) { issue(ch + 1, (ch + 1) & 1); CP_WAIT1(); }
        else CP_WAIT0();
        __syncthreads();
        uint32_t d = s0 + st * STG;
        #pragma unroll
        for (int kk = 0; kk < 2; kk++) {
            uint32_t ah[FM][4];
            #pragma unroll
            for (int f = 0; f < FM; f++) {
                uint32_t a = d + (wm*WM + f*16 + lrow)*ROWB + lhalf*16 + kk*32;
                LDSM4(ah[f], a);
            }
            #pragma unroll
            for (int gg = 0; gg < NF; gg += GG) {
                uint32_t bh[GG][2];
                #pragma unroll
                for (int g2 = 0; g2 < GG; g2 += 2) {
                    int g = gg + g2;
                    uint32_t b = d + ASZ + (wn*WN + g*8 + lrow)*ROWB + lhalf*16 + kk*32;
                    uint32_t t4[4];
                    LDSM4(t4, b);
                    bh[g2][0]=t4[0]; bh[g2][1]=t4[2]; bh[g2+1][0]=t4[1]; bh[g2+1][1]=t4[3];
                }
                #pragma unroll
                for (int f = 0; f < FM; f++)
                    #pragma unroll
                    for (int g2 = 0; g2 < GG; g2++)
                        mmaop_h(acc[f][gg+g2], ah[f], bh[g2]);
            }
        }
        __syncthreads();
    }
    #pragma unroll
    for (int f = 0; f < FM; f++)
        #pragma unroll
        for (int g = 0; g < NF; g++) {
            int r = m0 + wm*WM + f*16 + (lane >> 2);
            int c = n0 + wn*WN + g*8 + (lane & 3)*2;
            epi(r,     c, acc[f][g][0], acc[f][g][1]);
            epi(r + 8, c, acc[f][g][2], acc[f][g][3]);
        }
}

// ---- 1-term fp16 GEMM, 3-stage KT=64 (scan) ----
#define ROWC 144
template<int TM, int TN, typename Epi>
__device__ __forceinline__ void gemm1_3s(
    const __half* __restrict__ A, int lda, int m0,
    const __half* __restrict__ B, int ldb, int n0, int K, Epi epi)
{
    extern __shared__ char smem[];
    constexpr int ASZ = TM * ROWC, BSZ = TN * ROWC, STG = ASZ + BSZ;
    constexpr int WM = TM / 4, WN = TN / 2, FM = WM / 16, NF = WN / 8;
    const uint32_t s0 = smem_u32(smem);
    const int tid = threadIdx.x, lane = tid & 31, wid = tid >> 5;
    const int wm = wid >> 1, wn = wid & 1;
    const int lrow = lane & 15, lhalf = lane >> 4;
    float acc[FM][NF][4] = {};

    auto issue = [&](int ch, int st) {
        uint32_t d = s0 + st * STG;
        int k0 = ch * 64;
        #pragma unroll
        for (int v = tid; v < TM * 8; v += 256) {
            int row = v >> 3, c = v & 7;
            cpasync16(d + row*ROWC + c*16, A + (m0+row)*lda + k0 + c*8);
        }
        #pragma unroll
        for (int v = tid; v < TN * 8; v += 256) {
            int row = v >> 3, c = v & 7;
            cpasync16(d + ASZ + row*ROWC + c*16, B + (n0+row)*ldb + k0 + c*8);
        }
        CP_COMMIT();
    };

    const int NC = K / 64;
    issue(0, 0);
    issue(1, 1);
    for (int ch = 0; ch < NC; ch++) {
        if (ch + 2 < NC) { issue(ch + 2, (ch + 2) % 3); CP_WAIT2(); }
        else if (ch + 1 < NC) CP_WAIT1();
        else CP_WAIT0();
        __syncthreads();
        uint32_t d = s0 + (ch % 3) * STG;
        #pragma unroll
        for (int kk = 0; kk < 4; kk++) {
            uint32_t ah[FM][4], bh[NF][2];
            #pragma unroll
            for (int f = 0; f < FM; f++) {
                uint32_t a = d + (wm*WM + f*16 + lrow)*ROWC + lhalf*16 + kk*32;
                LDSM4(ah[f], a);
            }
            #pragma unroll
            for (int g = 0; g < NF; g += 2) {
                uint32_t b = d + ASZ + (wn*WN + g*8 + lrow)*ROWC + lhalf*16 + kk*32;
                uint32_t t4[4];
                LDSM4(t4, b);
                bh[g][0]=t4[0]; bh[g][1]=t4[2]; bh[g+1][0]=t4[1]; bh[g+1][1]=t4[3];
            }
            #pragma unroll
            for (int f = 0; f < FM; f++)
                #pragma unroll
                for (int g = 0; g < NF; g++)
                    mmaop_h(acc[f][g], ah[f], bh[g]);
        }
        __syncthreads();
    }
    #pragma unroll
    for (int f = 0; f < FM; f++)
        #pragma unroll
        for (int g = 0; g < NF; g++) {
            int r = m0 + wm*WM + f*16 + (lane >> 2);
            int c = n0 + wn*WN + g*8 + (lane & 3)*2;
            epi(r,     c, acc[f][g][0], acc[f][g][1]);
            epi(r + 8, c, acc[f][g][2], acc[f][g][3]);
        }
}
#define SMEM_S  (2 * (2*64*ROWB + 2*32*ROWB))      // 30720 (init 3-term)
#define S1_3    (3 * (64*ROWC + 32*ROWC))          // 41472 (scan 1-term 3-stage)
#define S1_2    (2 * (128*ROWB + 128*ROWB))        // 40960 (xpre/logits 1-term)

// ---- prepack ----
__global__ __launch_bounds__(256) void pk_T(const float* __restrict__ src,
                                            bf16* __restrict__ dh, bf16* __restrict__ dl,
                                            int K, int N)
{
    __shared__ float tile[32][33];
    int kb = blockIdx.y * 32, nb = blockIdx.x * 32;
    int tx = threadIdx.x & 31, ty = threadIdx.x >> 5;
    for (int i = ty; i < 32; i += 8)
        tile[i][tx] = src[(kb + i) * N + nb + tx];
    __syncthreads();
    for (int i = ty; i < 32; i += 8) {
        int n = nb + i, k = kb + tx;
        float x = tile[tx][i];
        bf16 h = __float2bfloat16(x);
        dh[n * K + k] = h;
        dl[n * K + k] = __float2bfloat16(x - __bfloat162float(h));
    }
}
__global__ __launch_bounds__(256) void pk_gruH(const float* __restrict__ Wu,
                                               const float* __restrict__ Wr,
                                               const float* __restrict__ Wc)
{
    __shared__ float tile[32][33];
    int z = blockIdx.z;
    int gate = (z < 3) ? z : z - 3, layer = z / 3;
    const float* src = ((gate == 0) ? Wu : (gate == 1) ? Wr : Wc) + layer * 1024 * Hh;
    int kb = blockIdx.y * 32, nb = blockIdx.x * 32;
    int tx = threadIdx.x & 31, ty = threadIdx.x >> 5;
    for (int i = ty; i < 32; i += 8)
        tile[i][tx] = src[(kb + i) * Hh + nb + tx];
    __syncthreads();
    for (int i = ty; i < 32; i += 8)
        g_WgruH[z*SZGRU + (nb + i) * 1024 + kb + tx] = __float2half_rn(tile[tx][i]);
}
__global__ __launch_bounds__(256) void pk_Wo(const float* __restrict__ src)
{
    __shared__ float tile[32][33];
    int kb = blockIdx.y * 32, nb = blockIdx.x * 32;
    int tx = threadIdx.x & 31, ty = threadIdx.x >> 5;
    for (int i = ty; i < 32; i += 8) {
        int n = nb + tx;
        tile[i][tx] = (n < Vv) ? src[(kb + i) * Vv + n] : 0.f;
    }
    __syncthreads();
    for (int i = ty; i < 32; i += 8)
        g_WoH[(nb + i) * Hh + kb + tx] = __float2half_rn(tile[tx][i]);
}
__global__ __launch_bounds__(256) void pk_vgg(const float* __restrict__ src)
{
    int i = (blockIdx.x * 256 + threadIdx.x) * 2;
    sp2(g_vgg_h, g_vgg_l, i, src[i], src[i + 1]);
}
__global__ __launch_bounds__(256) void k_gather(const float* __restrict__ emb,
                                                const int* __restrict__ tok)
{
    int idx = (blockIdx.x * 256 + threadIdx.x) * 2;
    int r = idx >> 9, e = idx & 511;
    int token = tok[(r & 127) * Tt + (r >> 7)];
    sph(g_xembH, idx, emb[token * Hh + e], emb[token * Hh + e + 1]);
}

// ---- init: split-K partials then finalize ----
__global__ __launch_bounds__(256, 1) void k_initp()
{
    int cta = blockIdx.x;
    int ks = cta >> 5, mt = (cta >> 4) & 1, nt = cta & 15;
    int koff = ks * 1024;
    float* out = g_ipart[ks];
    mma_gemm<64,32>(g_vgg_h + koff, g_vgg_l + koff, Ff, mt*64,
                    g_Win_h + koff, g_Win_l + koff, Ff, nt*32, 1024,
        [&](int r, int c, float v0, float v1) {
            out[r*Hh + c] = v0; out[r*Hh + c + 1] = v1;
        });
}
__global__ __launch_bounds__(256) void k_initf(const float* __restrict__ b_in)
{
    if (blockIdx.x == 0 && threadIdx.x == 0) g_cnt = 0;   // reset scan barrier
    int i = (blockIdx.x * 256 + threadIdx.x) * 2;
    float v0 = tanhf(g_ipart[0][i] + g_ipart[1][i] + g_ipart[2][i] + g_ipart[3][i]
                     + b_in[i & 511]);
    float v1 = tanhf(g_ipart[0][i+1] + g_ipart[1][i+1] + g_ipart[2][i+1] + g_ipart[3][i+1]
                     + b_in[(i+1) & 511]);
    g_h0f[i] = v0; g_h0f[i+1] = v1;
    g_h1f[i] = v0; g_h1f[i+1] = v1;
    sph(g_h0H, i, v0, v1);
    int ci = (i >> 9) * 1024 + 512 + (i & 511);
    sph(g_c1H, ci, v0, v1);
}

// ---- layer0 x-projections for all t (128x128, 1-term fp16) ----
__global__ __launch_bounds__(256, 2) void k_xpre(const float* __restrict__ bu,
                                                 const float* __restrict__ br,
                                                 const float* __restrict__ bc)
{
    int n0 = blockIdx.x * 128, m0 = blockIdx.y * 128, gate = blockIdx.z;
    const float* bi = (gate == 0) ? bu : (gate == 1) ? br : bc;
    float* out = (gate == 0) ? g_Xu0 : (gate == 1) ? g_Xr0 : g_Xc0;
    gemm1_2s<128,128>(g_xembH, Hh, m0, g_WgruH + gate*SZGRU, 1024, n0, Hh,
        [&](int r, int c, float v0, float v1) {
            float2 val = make_float2(v0 + bi[c], v1 + bi[c + 1]);
            *(float2*)&out[r*Hh + c] = val;
        });
}

// ---- phase bodies (no returns — callers must hit the grid barrier) ----
__device__ __forceinline__ void ur_body(int w, int nt, int mt, int z,
                                        const float* bu1, const float* br1)
{
    int n0 = nt * 32;
    if (z < 2) {
        if (w < Tt) {
            int gate = z;
            const float* X = (gate ? g_Xr0 : g_Xu0) + w * BH;
            gemm1_3s<64,32>(g_h0H, Hh, mt*64,
                g_WgruH + gate*SZGRU + 512, 1024, n0, Hh,
                [&](int r, int c, float v0, float v1) {
                    int idx = r*Hh + c;
                    float s0 = sigmoidf_(v0 + X[idx]);
                    float s1 = sigmoidf_(v1 + X[idx+1]);
                    if (gate == 0) { g_u0f[idx] = s0; g_u0f[idx+1] = s1; }
                    else sph(g_rh0H, idx, s0*g_h0f[idx], s1*g_h0f[idx+1]);
                });
        }
    } else {
        if (w >= 1) {
            int gate = z - 2, par = (w - 1) & 1;
            const float* bi = gate ? br1 : bu1;
            gemm1_3s<64,32>(g_c1H, 1024, mt*64,
                g_WgruH + (3+gate)*SZGRU, 1024, n0, 1024,
                [&](int r, int c, float v0, float v1) {
                    int idx = r*Hh + c;
                    float s0 = sigmoidf_(v0 + bi[c]);
                    float s1 = sigmoidf_(v1 + bi[c+1]);
                    if (gate == 0) { g_u1f[idx] = s0; g_u1f[idx+1] = s1; }
                    else sph(g_c2H[par], r*1024 + 512 + c,
                             s0*g_h1f[idx], s1*g_h1f[idx+1]);
                });
        }
    }
}

__device__ __forceinline__ void c_body(int w, int nt, int mt, int z,
                                       const float* bc1)
{
    int n0 = nt * 32;
    if (z == 0) {
        if (w < Tt) {
            int par = w & 1;
            const float* Xc = g_Xc0 + w * BH;
            gemm1_3s<64,32>(g_rh0H, Hh, mt*64,
                g_WgruH + 2*SZGRU + 512, 1024, n0, Hh,
                [&](int r, int c, float v0, float v1) {
                    int idx = r*Hh + c;
                    float c0 = tanhf(v0 + Xc[idx]), c1 = tanhf(v1 + Xc[idx+1]);
                    float u0 = g_u0f[idx], u1 = g_u0f[idx+1];
                    float h0 = u0*g_h0f[idx]   + (1.f-u0)*c0;
                    float h1 = u1*g_h0f[idx+1] + (1.f-u1)*c1;
                    g_h0f[idx] = h0; g_h0f[idx+1] = h1;
                    sph(g_h0H, idx, h0, h1);
                    int ci = r*1024 + c;
                    sph(g_c1H, ci, h0, h1);
                    sph(g_c2H[par], ci, h0, h1);
                });
        }
    } else if (z == 1) {
        if (w >= 1) {
            int par = (w - 1) & 1;
            gemm1_3s<64,32>(g_c2H[par], 1024, mt*64,
                g_WgruH + 5*SZGRU, 1024, n0, 1024,
                [&](int r, int c, float v0, float v1) {
                    int idx = r*Hh + c;
                    float c0 = tanhf(v0 + bc1[c]), c1 = tanhf(v1 + bc1[c+1]);
                    float u0 = g_u1f[idx], u1 = g_u1f[idx+1];
                    float h0 = u0*g_h1f[idx]   + (1.f-u0)*c0;
                    float h1 = u1*g_h1f[idx+1] + (1.f-u1)*c1;
                    g_h1f[idx] = h0; g_h1f[idx+1] = h1;
                    sph(g_c1H, r*1024 + 512 + c, h0, h1);
                    sph(g_X1ah, ((w-1)*Bb + r)*Hh + c, h0, h1);
                });
        }
    }
}

// ---- persistent cooperative scan: 31 waves x 2 phases ----
__global__ __launch_bounds__(256, 1) void k_scan(const float* __restrict__ bu1,
                                                 const float* __restrict__ br1,
                                                 const float* __restrict__ bc1)
{
    const int cta = blockIdx.x;                 // 128 CTAs
    const int nt = cta & 15, mt = (cta >> 4) & 1, z = cta >> 5;
    unsigned bar = 0;
    for (int w = 0; w <= Tt; w++) {
        ur_body(w, nt, mt, z, bu1, br1);
        bar++; gbar(bar * 128);
        c_body(w, nt, mt, z, bc1);
        bar++; gbar(bar * 128);
    }
}

// ---- logits: 1-term fp16 ----
__global__ __launch_bounds__(256, 2) void k_logits(const float* __restrict__ bout,
                                                   float* __restrict__ out)
{
    int n0 = blockIdx.x * 128, m0 = blockIdx.y * 128;
    gemm1_2s<128,128>(g_X1ah, Hh, m0, g_WoH, Hh, n0, Hh,
        [&](int r, int c, float v0, float v1) {
            if (c < Vv) {
                int t = r >> 7, b = r & 127;
                long long base = (long long)(b * Tt + t) * Vv;
                out[base + c] = v0 + bout[c];
                if (c + 1 < Vv) out[base + c + 1] = v1 + bout[c + 1];
            }
        });
}

__global__ __launch_bounds__(256) void k_final(float* __restrict__ out)
{
    int i = blockIdx.x * 256 + threadIdx.x;
    out[(long long)Bb * Tt * Vv + i] = (i >> 16) ? g_h1f[i & (BH-1)] : g_h0f[i & (BH-1)];
}

// ---- launch ----
extern "C" void kernel_launch(void* const* d_in, const int* in_sizes, int n_in,
                              void* d_out, int out_size)
{
    const float* vgg   = (const float*)d_in[0];
    const int*   xTok  = (const int*)  d_in[1];
    const float* emb   = (const float*)d_in[2];
    const float* W_in  = (const float*)d_in[3];
    const float* b_in  = (const float*)d_in[4];
    const float* Wu    = (const float*)d_in[5];
    const float* bu    = (const float*)d_in[6];
    const float* Wr    = (const float*)d_in[7];
    const float* br    = (const float*)d_in[8];
    const float* Wc    = (const float*)d_in[9];
    const float* bc    = (const float*)d_in[10];
    const float* W_out = (const float*)d_in[11];
    const float* b_out = (const float*)d_in[12];
    float* out = (float*)d_out;

    static cudaStream_t s2 = nullptr;
    static cudaEvent_t evFork, evB, evScan, evFin;
    if (s2 == nullptr) {
        cudaStreamCreateWithFlags(&s2, cudaStreamNonBlocking);
        cudaEventCreateWithFlags(&evFork, cudaEventDisableTiming);
        cudaEventCreateWithFlags(&evB,    cudaEventDisableTiming);
        cudaEventCreateWithFlags(&evScan, cudaEventDisableTiming);
        cudaEventCreateWithFlags(&evFin,  cudaEventDisableTiming);
    }

    cudaFuncSetAttribute(k_xpre,   cudaFuncAttributeMaxDynamicSharedMemorySize, S1_2);
    cudaFuncSetAttribute(k_logits, cudaFuncAttributeMaxDynamicSharedMemorySize, S1_2);
    cudaFuncSetAttribute(k_scan,   cudaFuncAttributeMaxDynamicSharedMemorySize, S1_3);

    bf16 *Wih, *Wil;
    cudaGetSymbolAddress((void**)&Wih, g_Win_h);
    cudaGetSymbolAddress((void**)&Wil, g_Win_l);

    // fork: chain B (GRU weights + gather + xpre) and pk_Wo on side stream
    cudaEventRecord(evFork, 0);
    cudaStreamWaitEvent(s2, evFork, 0);
    pk_gruH<<<dim3(16, 32, 6), 256, 0, s2>>>(Wu, Wr, Wc);
    k_gather<<<(TBH/2)/256, 256, 0, s2>>>(emb, xTok);
    k_xpre<<<dim3(4, Tt*Bb/128, 3), 256, S1_2, s2>>>(bu, br, bc);
    pk_Wo<<<dim3(Vpad/32, 16), 256, 0, s2>>>(W_out);

    // chain A on main: vgg prepack + init hidden state (+ barrier reset)
    pk_vgg<<<(Bb*Ff/2)/256, 256>>>(vgg);
    pk_T<<<dim3(16, 128), 256>>>(W_in, Wih, Wil, Ff, Hh);
    k_initp<<<128, 256, SMEM_S>>>();
    k_initf<<<(BH/2)/256, 256>>>(b_in);

    // join B before scan
    cudaEventRecord(evB, s2);
    cudaStreamWaitEvent(0, evB, 0);

    // persistent cooperative scan (single launch, grid barriers inside)
    {
        const float* bu1 = bu + Hh;
        const float* br1 = br + Hh;
        const float* bc1 = bc + Hh;
        void* args[] = { (void*)&bu1, (void*)&br1, (void*)&bc1 };
        cudaLaunchCooperativeKernel((void*)k_scan, dim3(128), dim3(256),
                                    args, S1_3, (cudaStream_t)0);
    }

    // k_final on side stream concurrent with logits (disjoint output regions)
    cudaEventRecord(evScan, 0);
    cudaStreamWaitEvent(s2, evScan, 0);
    k_final<<<(2*BH)/256, 256, 0, s2>>>(out);

    k_logits<<<dim3(Vpad/128, Tt*Bb/128), 256, S1_2>>>(b_out, out);

    cudaEventRecord(evFin, s2);
    cudaStreamWaitEvent(0, evFin, 0);
}